// round 11
// baseline (speedup 1.0000x reference)
#include <cuda_runtime.h>

#define BB    64
#define CC    256
#define DDIM  256
#define HW    784
#define ATTRN 300
#define O1    32
#define ASTRIDE 36   // floats per c-row of g_A (32 o + 4 pad, 16B-aligned)

typedef unsigned long long ull_t;

// scratch (device globals — no allocation allowed)
__device__ float g_emb[BB * CC];             // s1-scaled embedding
__device__ float g_A[BB * CC * ASTRIDE];     // A matrix per batch

// ---- packed f32x2 helpers -------------------------------------------------
__device__ __forceinline__ ull_t fma2(ull_t a, ull_t b, ull_t c) {
    ull_t d;
    asm("fma.rn.f32x2 %0, %1, %2, %3;" : "=l"(d) : "l"(a), "l"(b), "l"(c));
    return d;
}
__device__ __forceinline__ ull_t pack2(float x) {
    ull_t d;
    asm("mov.b64 %0, {%1, %1};" : "=l"(d) : "f"(x));
    return d;
}
__device__ __forceinline__ float2 unpk2(ull_t v) {
    float2 r;
    asm("mov.b64 {%0, %1}, %2;" : "=f"(r.x), "=f"(r.y) : "l"(v));
    return r;
}

// ---------------------------------------------------------------------------
// Kernel 1: g_emb[b,c] = s1[c] * (W_emb[c]·attr[b] + b_emb[c])
// grid = 128 blocks (64 c-groups x 2 b-halves), 128 threads (32 b x 4 c)
// ---------------------------------------------------------------------------
__global__ void __launch_bounds__(128) k1_emb(
    const float* __restrict__ attr_oh,   // [B, ATTR]
    const float* __restrict__ W_emb,     // [C, ATTR]
    const float* __restrict__ b_emb,
    const float* __restrict__ s1)
{
    extern __shared__ float sh1[];
    float* attr_s = sh1;                  // [32*300]
    float* Ws     = sh1 + 32 * ATTRN;     // [4*300]
    int tid = threadIdx.x;
    int bh  = blockIdx.x & 1;
    int c0  = (blockIdx.x >> 1) * 4;

    {
        const float4* src = (const float4*)(attr_oh + (size_t)bh * 32 * ATTRN);
        float4* dst = (float4*)attr_s;
        for (int i = tid; i < 32 * (ATTRN / 4); i += 128) dst[i] = src[i];
        const float4* wsrc = (const float4*)(W_emb + (size_t)c0 * ATTRN);
        float4* wdst = (float4*)Ws;
        for (int i = tid; i < 4 * (ATTRN / 4); i += 128) wdst[i] = wsrc[i];
    }
    __syncthreads();

    int bl = tid & 31;
    int ci = tid >> 5;                    // warp-uniform
    const ulonglong2* ar = (const ulonglong2*)(attr_s + bl * ATTRN);
    const ulonglong2* wr = (const ulonglong2*)(Ws + ci * ATTRN);

    ull_t acc0 = 0ull, acc1 = 0ull;
#pragma unroll 5
    for (int k = 0; k < ATTRN / 4; k++) {
        ulonglong2 av = ar[k];
        ulonglong2 wv = wr[k];            // warp-uniform broadcast
        acc0 = fma2(wv.x, av.x, acc0);
        acc1 = fma2(wv.y, av.y, acc1);
    }
    float2 f0 = unpk2(acc0), f1 = unpk2(acc1);
    int c = c0 + ci;
    int b = bh * 32 + bl;
    g_emb[b * CC + c] = s1[c] * ((f0.x + f0.y) + (f1.x + f1.y) + b_emb[c]);
}

// ---------------------------------------------------------------------------
// Kernel 2: CM tile in registers -> direct h2-gather to g_A (k2b folded in).
//   CM[b,o,m] = sum_k W[o,k] * sa[b,(k-m)&255]
//   then for c with h2[c] in this m-tile: g_A[b][c][o] = s2[c]*CM[b][o][h2[c]]
// grid = (8 m-tiles, 16 batch-groups), 256 threads
// ---------------------------------------------------------------------------
__global__ void __launch_bounds__(256) k2_cm(
    const float* __restrict__ conv1_w,   // [32,256]
    const int*   __restrict__ h1,        // [256]
    const int*   __restrict__ h2,        // [256]
    const float* __restrict__ s2)        // [256]
{
    extern __shared__ char sm2[];
    float* wtmp = (float*)sm2;                          // [32*257], reused as cms
    float* wdT  = (float*)(sm2 + 32 * 257 * 4);         // [256*32]
    ull_t* sa2  = (ull_t*)(sm2 + 32 * 257 * 4 + 32768); // [2][512]
    int tid = threadIdx.x;
    int mt  = blockIdx.x;
    int b0  = blockIdx.y * 4;

    for (int i = tid; i < O1 * DDIM; i += 256) {
        int o = i >> 8, k = i & 255;
        wtmp[o * 257 + k] = conv1_w[i];
    }
    for (int i = tid; i < 2 * DDIM; i += 256) {
        sa2[(i >> 8) * 512 + 256 + (i & 255)] = 0ull;
    }
    __syncthreads();

    for (int i = tid; i < O1 * DDIM; i += 256) {
        int o = i & 31, k = i >> 5;
        wdT[k * 32 + o] = wtmp[o * 257 + k];
    }
    {
        int hv = h1[tid];
#pragma unroll
        for (int p = 0; p < 2; p++) {
            float vx = g_emb[(b0 + 2 * p)     * CC + tid];
            float vy = g_emb[(b0 + 2 * p + 1) * CC + tid];
            float2* slot = (float2*)&sa2[p * 512 + 256 + hv];
            atomicAdd(&slot->x, vx);
            atomicAdd(&slot->y, vy);
        }
    }
    __syncthreads();

    for (int i = tid; i < 2 * DDIM; i += 256) {
        int p = i >> 8, j = i & 255;
        sa2[p * 512 + j] = sa2[p * 512 + 256 + j];
    }
    __syncthreads();

    int ml = tid & 31;
    int m  = mt * 32 + ml;
    int o0 = (tid >> 5) << 2;            // warp-uniform o quad
    const ull_t* s0p = sa2 + (256 - m);
    const ull_t* s1p = sa2 + 512 + (256 - m);

    ull_t acc[2][4];
#pragma unroll
    for (int p = 0; p < 2; p++)
#pragma unroll
        for (int oo = 0; oo < 4; oo++) acc[p][oo] = 0ull;

#pragma unroll 8
    for (int k = 0; k < DDIM; k++) {
        float4 wv = *(const float4*)&wdT[k * 32 + o0];   // uniform, 1 phase
        ull_t s0 = s0p[k], s1v = s1p[k];
        ull_t w0 = pack2(wv.x), w1 = pack2(wv.y);
        ull_t w2 = pack2(wv.z), w3 = pack2(wv.w);
        acc[0][0] = fma2(w0, s0,  acc[0][0]);
        acc[0][1] = fma2(w1, s0,  acc[0][1]);
        acc[0][2] = fma2(w2, s0,  acc[0][2]);
        acc[0][3] = fma2(w3, s0,  acc[0][3]);
        acc[1][0] = fma2(w0, s1v, acc[1][0]);
        acc[1][1] = fma2(w1, s1v, acc[1][1]);
        acc[1][2] = fma2(w2, s1v, acc[1][2]);
        acc[1][3] = fma2(w3, s1v, acc[1][3]);
    }

    // deposit CM tile to smem (reuse wtmp region): cms4[o][ml] = float4 over b
    float4* cms4 = (float4*)wtmp;        // [32][33] padded
#pragma unroll
    for (int p = 0; p < 2; p++)
#pragma unroll
        for (int oo = 0; oo < 4; oo++) {
            float2 f = unpk2(acc[p][oo]);
            float* base = (float*)&cms4[(o0 + oo) * 33 + ml];
            base[2 * p]     = f.x;
            base[2 * p + 1] = f.y;
        }
    __syncthreads();

    // gather: thread = channel c; active if h2[c] lands in this m-tile
    {
        int c   = tid;
        int hv2 = h2[c];
        if ((hv2 >> 5) == mt) {
            int   ml2 = hv2 & 31;
            float sc  = s2[c];
#pragma unroll
            for (int bi = 0; bi < 4; bi++) {
                float* Ab = g_A + ((size_t)(b0 + bi) * CC + c) * ASTRIDE;
#pragma unroll
                for (int o8 = 0; o8 < 8; o8++) {
                    float4 w;
                    w.x = sc * ((float*)&cms4[(o8 * 4 + 0) * 33 + ml2])[bi];
                    w.y = sc * ((float*)&cms4[(o8 * 4 + 1) * 33 + ml2])[bi];
                    w.z = sc * ((float*)&cms4[(o8 * 4 + 2) * 33 + ml2])[bi];
                    w.w = sc * ((float*)&cms4[(o8 * 4 + 3) * 33 + ml2])[bi];
                    *(float4*)(Ab + o8 * 4) = w;
                }
            }
        }
    }
}

// ---------------------------------------------------------------------------
// Kernel 3: fused GEMM + sigmoid + broadcast multiply.
// 8 warps = (c-half, og); forced 4 blocks/SM (regs<=64) -> 32 warps/SM.
// grid = (7 tiles, 64 batches), ~56KB smem
// ---------------------------------------------------------------------------
__global__ void __launch_bounds__(256, 4) k3_main(
    const float* __restrict__ x,        // [B, C, HW]
    const float* __restrict__ conv2_w,  // [32]
    float* __restrict__ out_map,        // [B, HW]
    float* __restrict__ out_feat)       // [B, C, HW]
{
    extern __shared__ char sm3[];
    float*  As    = (float*)sm3;                            // [256*36] 36,864B
    ull_t*  part  = (ull_t*)(sm3 + CC * ASTRIDE * 4);       // [16][128] 16,384B
    float4* red4  = (float4*)((char*)part + 16 * 128 * 8);  // [128] 2,048B
    float4* marr4 = (float4*)((char*)red4 + 128 * 16);      // [32]
    float*  w2s   = (float*)((char*)marr4 + 32 * 16);       // [32]

    int b    = blockIdx.y;
    int tile = blockIdx.x;
    int tid  = threadIdx.x;
    int ql   = tid & 31;            // quad lane
    int warp = tid >> 5;
    int og   = warp & 3;            // warp-uniform: 8 o's
    int ch   = warp >> 2;           // c-half 0/1

    {   // stage A (pure float4 copy)
        const float4* src = (const float4*)(g_A + (size_t)b * CC * ASTRIDE);
        float4* dst = (float4*)As;
        for (int i = tid; i < CC * ASTRIDE / 4; i += 256) dst[i] = src[i];
    }
    if (tid < O1) w2s[tid] = conv2_w[tid];
    __syncthreads();

    int q = tile * 32 + ql;
    bool valid = q < (HW / 4);           // 196 valid quads
    int p = valid ? q * 4 : 0;
    const float* xb = x + (size_t)b * CC * HW;

    ull_t acc[4][4];                     // [pos][o-pair]
#pragma unroll
    for (int pp = 0; pp < 4; pp++)
#pragma unroll
        for (int j = 0; j < 4; j++) acc[pp][j] = 0ull;

    const float* Abase = As + og * 8;
    int cbeg = ch * 128;

#pragma unroll 4
    for (int ci = 0; ci < 128; ci++) {
        int c = cbeg + ci;
        float4 xf = *(const float4*)(xb + (size_t)c * HW + p);
        ulonglong2 a01_23 = *(const ulonglong2*)(Abase + c * ASTRIDE);
        ulonglong2 a45_67 = *(const ulonglong2*)(Abase + c * ASTRIDE + 4);
        ull_t xd0 = pack2(xf.x), xd1 = pack2(xf.y);
        ull_t xd2 = pack2(xf.z), xd3 = pack2(xf.w);
        acc[0][0] = fma2(a01_23.x, xd0, acc[0][0]);
        acc[1][0] = fma2(a01_23.x, xd1, acc[1][0]);
        acc[2][0] = fma2(a01_23.x, xd2, acc[2][0]);
        acc[3][0] = fma2(a01_23.x, xd3, acc[3][0]);
        acc[0][1] = fma2(a01_23.y, xd0, acc[0][1]);
        acc[1][1] = fma2(a01_23.y, xd1, acc[1][1]);
        acc[2][1] = fma2(a01_23.y, xd2, acc[2][1]);
        acc[3][1] = fma2(a01_23.y, xd3, acc[3][1]);
        acc[0][2] = fma2(a45_67.x, xd0, acc[0][2]);
        acc[1][2] = fma2(a45_67.x, xd1, acc[1][2]);
        acc[2][2] = fma2(a45_67.x, xd2, acc[2][2]);
        acc[3][2] = fma2(a45_67.x, xd3, acc[3][2]);
        acc[0][3] = fma2(a45_67.y, xd0, acc[0][3]);
        acc[1][3] = fma2(a45_67.y, xd1, acc[1][3]);
        acc[2][3] = fma2(a45_67.y, xd2, acc[2][3]);
        acc[3][3] = fma2(a45_67.y, xd3, acc[3][3]);
    }

    // combine c-halves: ch1 deposits partials; ch0 adds (layout [j16][t128])
    if (ch == 1) {
        int t = tid - 128;
#pragma unroll
        for (int pp = 0; pp < 4; pp++)
#pragma unroll
            for (int j = 0; j < 4; j++)
                part[(pp * 4 + j) * 128 + t] = acc[pp][j];
    }
    __syncthreads();

    if (ch == 0) {
        ull_t one = pack2(1.0f);
#pragma unroll
        for (int pp = 0; pp < 4; pp++)
#pragma unroll
            for (int j = 0; j < 4; j++)
                acc[pp][j] = fma2(one, part[(pp * 4 + j) * 128 + tid], acc[pp][j]);

        float4 ps;
        float* psf = (float*)&ps;
#pragma unroll
        for (int pp = 0; pp < 4; pp++) {
            float s = 0.f;
#pragma unroll
            for (int j = 0; j < 4; j++) {
                float2 h = unpk2(acc[pp][j]);
                s = fmaf(w2s[og * 8 + 2 * j],     fmaxf(h.x, 0.f), s);
                s = fmaf(w2s[og * 8 + 2 * j + 1], fmaxf(h.y, 0.f), s);
            }
            psf[pp] = s;
        }
        red4[tid] = ps;
    }
    __syncthreads();

    if (tid < 32) {
        float4 t0 = red4[tid], t1 = red4[tid + 32];
        float4 t2 = red4[tid + 64], t3 = red4[tid + 96];
        float4 t;
        t.x = (t0.x + t1.x) + (t2.x + t3.x);
        t.y = (t0.y + t1.y) + (t2.y + t3.y);
        t.z = (t0.z + t1.z) + (t2.z + t3.z);
        t.w = (t0.w + t1.w) + (t2.w + t3.w);
        float4 mm;
        mm.x = 1.f / (1.f + __expf(-t.x));
        mm.y = 1.f / (1.f + __expf(-t.y));
        mm.z = 1.f / (1.f + __expf(-t.z));
        mm.w = 1.f / (1.f + __expf(-t.w));
        marr4[tid] = mm;
        int qg = tile * 32 + tid;
        if (qg < (HW / 4)) *(float4*)(out_map + b * HW + qg * 4) = mm;
    }
    __syncthreads();

    // epilogue: feat = map * x (x re-read is L2-hot); warp c-stride 8
    if (valid) {
        float4 mm = marr4[ql];
        float* fb = out_feat + (size_t)b * CC * HW;
        for (int c = warp; c < CC; c += 8) {
            float4 xv = *(const float4*)(xb + (size_t)c * HW + p);
            float4 r;
            r.x = mm.x * xv.x; r.y = mm.y * xv.y;
            r.z = mm.z * xv.z; r.w = mm.w * xv.w;
            *(float4*)(fb + (size_t)c * HW + p) = r;
        }
    }
}

// ---------------------------------------------------------------------------
extern "C" void kernel_launch(void* const* d_in, const int* in_sizes, int n_in,
                              void* d_out, int out_size)
{
    (void)in_sizes; (void)n_in; (void)out_size;
    const float* x        = (const float*)d_in[0];
    const float* attr_oh  = (const float*)d_in[1];
    const float* W_emb    = (const float*)d_in[2];
    const float* b_emb    = (const float*)d_in[3];
    const int*   h1       = (const int*)  d_in[4];
    const float* s1       = (const float*)d_in[5];
    const int*   h2       = (const int*)  d_in[6];
    const float* s2       = (const float*)d_in[7];
    const float* conv1_w  = (const float*)d_in[8];
    const float* conv2_w  = (const float*)d_in[9];

    float* out      = (float*)d_out;
    float* out_map  = out;               // [64,784]
    float* out_feat = out + BB * HW;     // [64,256,784]

    const int sh1 = (32 * ATTRN + 4 * ATTRN) * 4;                   // ~43.2 KB
    const int sh2 = 32 * 257 * 4 + 32768 + 2 * 512 * 8;             // ~73.9 KB
    const int sh3 = CC * ASTRIDE * 4 + 16 * 128 * 8
                  + 128 * 16 + 32 * 16 + O1 * 4;                    // ~55.9 KB
    cudaFuncSetAttribute(k1_emb,  cudaFuncAttributeMaxDynamicSharedMemorySize, sh1);
    cudaFuncSetAttribute(k2_cm,   cudaFuncAttributeMaxDynamicSharedMemorySize, sh2);
    cudaFuncSetAttribute(k3_main, cudaFuncAttributeMaxDynamicSharedMemorySize, sh3);

    k1_emb<<<128, 128, sh1>>>(attr_oh, W_emb, b_emb, s1);
    k2_cm<<<dim3(8, 16), 256, sh2>>>(conv1_w, h1, h2, s2);
    k3_main<<<dim3(7, BB), 256, sh3>>>(x, conv2_w, out_map, out_feat);
}

// round 12
// speedup vs baseline: 1.0491x; 1.0491x over previous
#include <cuda_runtime.h>

#define BB    64
#define CC    256
#define DDIM  256
#define HW    784
#define ATTRN 300
#define O1    32
#define ASTRIDE 36   // floats per c-row of g_A (32 o + 4 pad, 16B-aligned)

typedef unsigned long long ull_t;

// scratch (device globals — no allocation allowed)
__device__ float g_emb[BB * CC];             // s1-scaled embedding
__device__ float g_A[BB * CC * ASTRIDE];     // A matrix per batch

// ---- packed f32x2 helpers -------------------------------------------------
__device__ __forceinline__ ull_t fma2(ull_t a, ull_t b, ull_t c) {
    ull_t d;
    asm("fma.rn.f32x2 %0, %1, %2, %3;" : "=l"(d) : "l"(a), "l"(b), "l"(c));
    return d;
}
__device__ __forceinline__ ull_t pack2(float x) {
    ull_t d;
    asm("mov.b64 %0, {%1, %1};" : "=l"(d) : "f"(x));
    return d;
}
__device__ __forceinline__ float2 unpk2(ull_t v) {
    float2 r;
    asm("mov.b64 {%0, %1}, %2;" : "=f"(r.x), "=f"(r.y) : "l"(v));
    return r;
}

// ---------------------------------------------------------------------------
// Kernel 1: g_emb[b,c] = s1[c] * (W_emb[c]·attr[b] + b_emb[c])
// PLUS: prefetch all of x (51.4MB, fits L2) so k3's GEMM stream hits L2.
// grid = 128 blocks (64 c-groups x 2 b-halves), 128 threads (32 b x 4 c)
// ---------------------------------------------------------------------------
__global__ void __launch_bounds__(128) k1_emb(
    const float* __restrict__ attr_oh,   // [B, ATTR]
    const float* __restrict__ W_emb,     // [C, ATTR]
    const float* __restrict__ b_emb,
    const float* __restrict__ s1,
    const float* __restrict__ x)         // [B, C, HW] — prefetch only
{
    extern __shared__ float sh1[];
    float* attr_s = sh1;                  // [32*300]
    float* Ws     = sh1 + 32 * ATTRN;     // [4*300]
    int tid = threadIdx.x;
    int bh  = blockIdx.x & 1;
    int c0  = (blockIdx.x >> 1) * 4;

    {
        const float4* src = (const float4*)(attr_oh + (size_t)bh * 32 * ATTRN);
        float4* dst = (float4*)attr_s;
        for (int i = tid; i < 32 * (ATTRN / 4); i += 128) dst[i] = src[i];
        const float4* wsrc = (const float4*)(W_emb + (size_t)c0 * ATTRN);
        float4* wdst = (float4*)Ws;
        for (int i = tid; i < 4 * (ATTRN / 4); i += 128) wdst[i] = wsrc[i];
    }
    __syncthreads();

    int bl = tid & 31;
    int ci = tid >> 5;                    // warp-uniform
    const ulonglong2* ar = (const ulonglong2*)(attr_s + bl * ATTRN);
    const ulonglong2* wr = (const ulonglong2*)(Ws + ci * ATTRN);

    ull_t acc0 = 0ull, acc1 = 0ull;
#pragma unroll 5
    for (int k = 0; k < ATTRN / 4; k++) {
        ulonglong2 av = ar[k];
        ulonglong2 wv = wr[k];            // warp-uniform broadcast
        acc0 = fma2(wv.x, av.x, acc0);
        acc1 = fma2(wv.y, av.y, acc1);
    }
    float2 f0 = unpk2(acc0), f1 = unpk2(acc1);
    int c = c0 + ci;
    int b = bh * 32 + bl;
    g_emb[b * CC + c] = s1[c] * ((f0.x + f0.y) + (f1.x + f1.y) + b_emb[c]);

    // warm x into L2: 51.4MB = 411,648 128B lines over 16,384 threads
    {
        const size_t nlines = (size_t)BB * CC * HW / 32;   // 4B floats, 32/line
        size_t gt = (size_t)blockIdx.x * 128 + tid;
        for (size_t l = gt; l < nlines; l += 128 * 128) {
            asm volatile("prefetch.global.L2 [%0];" :: "l"(x + l * 32));
        }
    }
}

// ---------------------------------------------------------------------------
// Kernel 2: CM tile in registers -> direct h2-gather to g_A (k2b folded in).
//   CM[b,o,m] = sum_k W[o,k] * sa[b,(k-m)&255]
//   then for c with h2[c] in this m-tile: g_A[b][c][o] = s2[c]*CM[b][o][h2[c]]
// grid = (8 m-tiles, 16 batch-groups), 256 threads
// ---------------------------------------------------------------------------
__global__ void __launch_bounds__(256) k2_cm(
    const float* __restrict__ conv1_w,   // [32,256]
    const int*   __restrict__ h1,        // [256]
    const int*   __restrict__ h2,        // [256]
    const float* __restrict__ s2)        // [256]
{
    extern __shared__ char sm2[];
    float* wtmp = (float*)sm2;                          // [32*257], reused as cms
    float* wdT  = (float*)(sm2 + 32 * 257 * 4);         // [256*32]
    ull_t* sa2  = (ull_t*)(sm2 + 32 * 257 * 4 + 32768); // [2][512]
    int tid = threadIdx.x;
    int mt  = blockIdx.x;
    int b0  = blockIdx.y * 4;

    for (int i = tid; i < O1 * DDIM; i += 256) {
        int o = i >> 8, k = i & 255;
        wtmp[o * 257 + k] = conv1_w[i];
    }
    for (int i = tid; i < 2 * DDIM; i += 256) {
        sa2[(i >> 8) * 512 + 256 + (i & 255)] = 0ull;
    }
    __syncthreads();

    for (int i = tid; i < O1 * DDIM; i += 256) {
        int o = i & 31, k = i >> 5;
        wdT[k * 32 + o] = wtmp[o * 257 + k];
    }
    {
        int hv = h1[tid];
#pragma unroll
        for (int p = 0; p < 2; p++) {
            float vx = g_emb[(b0 + 2 * p)     * CC + tid];
            float vy = g_emb[(b0 + 2 * p + 1) * CC + tid];
            float2* slot = (float2*)&sa2[p * 512 + 256 + hv];
            atomicAdd(&slot->x, vx);
            atomicAdd(&slot->y, vy);
        }
    }
    __syncthreads();

    for (int i = tid; i < 2 * DDIM; i += 256) {
        int p = i >> 8, j = i & 255;
        sa2[p * 512 + j] = sa2[p * 512 + 256 + j];
    }
    __syncthreads();

    int ml = tid & 31;
    int m  = mt * 32 + ml;
    int o0 = (tid >> 5) << 2;            // warp-uniform o quad
    const ull_t* s0p = sa2 + (256 - m);
    const ull_t* s1p = sa2 + 512 + (256 - m);

    ull_t acc[2][4];
#pragma unroll
    for (int p = 0; p < 2; p++)
#pragma unroll
        for (int oo = 0; oo < 4; oo++) acc[p][oo] = 0ull;

#pragma unroll 8
    for (int k = 0; k < DDIM; k++) {
        float4 wv = *(const float4*)&wdT[k * 32 + o0];   // uniform, 1 phase
        ull_t s0 = s0p[k], s1v = s1p[k];
        ull_t w0 = pack2(wv.x), w1 = pack2(wv.y);
        ull_t w2 = pack2(wv.z), w3 = pack2(wv.w);
        acc[0][0] = fma2(w0, s0,  acc[0][0]);
        acc[0][1] = fma2(w1, s0,  acc[0][1]);
        acc[0][2] = fma2(w2, s0,  acc[0][2]);
        acc[0][3] = fma2(w3, s0,  acc[0][3]);
        acc[1][0] = fma2(w0, s1v, acc[1][0]);
        acc[1][1] = fma2(w1, s1v, acc[1][1]);
        acc[1][2] = fma2(w2, s1v, acc[1][2]);
        acc[1][3] = fma2(w3, s1v, acc[1][3]);
    }

    // deposit CM tile to smem (reuse wtmp region): cms4[o][ml] = float4 over b
    float4* cms4 = (float4*)wtmp;        // [32][33] padded
#pragma unroll
    for (int p = 0; p < 2; p++)
#pragma unroll
        for (int oo = 0; oo < 4; oo++) {
            float2 f = unpk2(acc[p][oo]);
            float* base = (float*)&cms4[(o0 + oo) * 33 + ml];
            base[2 * p]     = f.x;
            base[2 * p + 1] = f.y;
        }
    __syncthreads();

    // gather: thread = channel c; active if h2[c] lands in this m-tile
    {
        int c   = tid;
        int hv2 = h2[c];
        if ((hv2 >> 5) == mt) {
            int   ml2 = hv2 & 31;
            float sc  = s2[c];
#pragma unroll
            for (int bi = 0; bi < 4; bi++) {
                float* Ab = g_A + ((size_t)(b0 + bi) * CC + c) * ASTRIDE;
#pragma unroll
                for (int o8 = 0; o8 < 8; o8++) {
                    float4 w;
                    w.x = sc * ((float*)&cms4[(o8 * 4 + 0) * 33 + ml2])[bi];
                    w.y = sc * ((float*)&cms4[(o8 * 4 + 1) * 33 + ml2])[bi];
                    w.z = sc * ((float*)&cms4[(o8 * 4 + 2) * 33 + ml2])[bi];
                    w.w = sc * ((float*)&cms4[(o8 * 4 + 3) * 33 + ml2])[bi];
                    *(float4*)(Ab + o8 * 4) = w;
                }
            }
        }
    }
}

// ---------------------------------------------------------------------------
// Kernel 3: fused GEMM + sigmoid + broadcast multiply.  (R10 proven body)
// 8 warps = (c-half, og); explicit x prefetch register. grid (7,64), ~56KB
// ---------------------------------------------------------------------------
__global__ void __launch_bounds__(256) k3_main(
    const float* __restrict__ x,        // [B, C, HW]
    const float* __restrict__ conv2_w,  // [32]
    float* __restrict__ out_map,        // [B, HW]
    float* __restrict__ out_feat)       // [B, C, HW]
{
    extern __shared__ char sm3[];
    float*  As    = (float*)sm3;                            // [256*36] 36,864B
    ull_t*  part  = (ull_t*)(sm3 + CC * ASTRIDE * 4);       // [16][128] 16,384B
    float4* red4  = (float4*)((char*)part + 16 * 128 * 8);  // [128] 2,048B
    float4* marr4 = (float4*)((char*)red4 + 128 * 16);      // [32]
    float*  w2s   = (float*)((char*)marr4 + 32 * 16);       // [32]

    int b    = blockIdx.y;
    int tile = blockIdx.x;
    int tid  = threadIdx.x;
    int ql   = tid & 31;            // quad lane
    int warp = tid >> 5;
    int og   = warp & 3;            // warp-uniform: 8 o's
    int ch   = warp >> 2;           // c-half 0/1

    {   // stage A (pure float4 copy)
        const float4* src = (const float4*)(g_A + (size_t)b * CC * ASTRIDE);
        float4* dst = (float4*)As;
        for (int i = tid; i < CC * ASTRIDE / 4; i += 256) dst[i] = src[i];
    }
    if (tid < O1) w2s[tid] = conv2_w[tid];
    __syncthreads();

    int q = tile * 32 + ql;
    bool valid = q < (HW / 4);           // 196 valid quads
    int p = valid ? q * 4 : 0;
    const float* xb = x + (size_t)b * CC * HW;

    ull_t acc[4][4];                     // [pos][o-pair]
#pragma unroll
    for (int pp = 0; pp < 4; pp++)
#pragma unroll
        for (int j = 0; j < 4; j++) acc[pp][j] = 0ull;

    const float* Abase = As + og * 8;
    int cbeg = ch * 128;

    float4 xf = *(const float4*)(xb + (size_t)cbeg * HW + p);
#pragma unroll 4
    for (int ci = 0; ci < 128; ci++) {
        int c  = cbeg + ci;
        int cn = c + (ci < 127 ? 1 : 0);
        float4 xn = *(const float4*)(xb + (size_t)cn * HW + p);  // prefetch
        ulonglong2 a01_23 = *(const ulonglong2*)(Abase + c * ASTRIDE);
        ulonglong2 a45_67 = *(const ulonglong2*)(Abase + c * ASTRIDE + 4);
        ull_t xd0 = pack2(xf.x), xd1 = pack2(xf.y);
        ull_t xd2 = pack2(xf.z), xd3 = pack2(xf.w);
        acc[0][0] = fma2(a01_23.x, xd0, acc[0][0]);
        acc[1][0] = fma2(a01_23.x, xd1, acc[1][0]);
        acc[2][0] = fma2(a01_23.x, xd2, acc[2][0]);
        acc[3][0] = fma2(a01_23.x, xd3, acc[3][0]);
        acc[0][1] = fma2(a01_23.y, xd0, acc[0][1]);
        acc[1][1] = fma2(a01_23.y, xd1, acc[1][1]);
        acc[2][1] = fma2(a01_23.y, xd2, acc[2][1]);
        acc[3][1] = fma2(a01_23.y, xd3, acc[3][1]);
        acc[0][2] = fma2(a45_67.x, xd0, acc[0][2]);
        acc[1][2] = fma2(a45_67.x, xd1, acc[1][2]);
        acc[2][2] = fma2(a45_67.x, xd2, acc[2][2]);
        acc[3][2] = fma2(a45_67.x, xd3, acc[3][2]);
        acc[0][3] = fma2(a45_67.y, xd0, acc[0][3]);
        acc[1][3] = fma2(a45_67.y, xd1, acc[1][3]);
        acc[2][3] = fma2(a45_67.y, xd2, acc[2][3]);
        acc[3][3] = fma2(a45_67.y, xd3, acc[3][3]);
        xf = xn;
    }

    // combine c-halves: ch1 deposits partials; ch0 adds (layout [j16][t128])
    if (ch == 1) {
        int t = tid - 128;
#pragma unroll
        for (int pp = 0; pp < 4; pp++)
#pragma unroll
            for (int j = 0; j < 4; j++)
                part[(pp * 4 + j) * 128 + t] = acc[pp][j];
    }
    __syncthreads();

    if (ch == 0) {
        ull_t one = pack2(1.0f);
#pragma unroll
        for (int pp = 0; pp < 4; pp++)
#pragma unroll
            for (int j = 0; j < 4; j++)
                acc[pp][j] = fma2(one, part[(pp * 4 + j) * 128 + tid], acc[pp][j]);

        float4 ps;
        float* psf = (float*)&ps;
#pragma unroll
        for (int pp = 0; pp < 4; pp++) {
            float s = 0.f;
#pragma unroll
            for (int j = 0; j < 4; j++) {
                float2 h = unpk2(acc[pp][j]);
                s = fmaf(w2s[og * 8 + 2 * j],     fmaxf(h.x, 0.f), s);
                s = fmaf(w2s[og * 8 + 2 * j + 1], fmaxf(h.y, 0.f), s);
            }
            psf[pp] = s;
        }
        red4[tid] = ps;
    }
    __syncthreads();

    if (tid < 32) {
        float4 t0 = red4[tid], t1 = red4[tid + 32];
        float4 t2 = red4[tid + 64], t3 = red4[tid + 96];
        float4 t;
        t.x = (t0.x + t1.x) + (t2.x + t3.x);
        t.y = (t0.y + t1.y) + (t2.y + t3.y);
        t.z = (t0.z + t1.z) + (t2.z + t3.z);
        t.w = (t0.w + t1.w) + (t2.w + t3.w);
        float4 mm;
        mm.x = 1.f / (1.f + __expf(-t.x));
        mm.y = 1.f / (1.f + __expf(-t.y));
        mm.z = 1.f / (1.f + __expf(-t.z));
        mm.w = 1.f / (1.f + __expf(-t.w));
        marr4[tid] = mm;
        int qg = tile * 32 + tid;
        if (qg < (HW / 4)) *(float4*)(out_map + b * HW + qg * 4) = mm;
    }
    __syncthreads();

    // epilogue: feat = map * x (x re-read is L2-hot); warp c-stride 8
    if (valid) {
        float4 mm = marr4[ql];
        float* fb = out_feat + (size_t)b * CC * HW;
        for (int c = warp; c < CC; c += 8) {
            float4 xv = *(const float4*)(xb + (size_t)c * HW + p);
            float4 r;
            r.x = mm.x * xv.x; r.y = mm.y * xv.y;
            r.z = mm.z * xv.z; r.w = mm.w * xv.w;
            *(float4*)(fb + (size_t)c * HW + p) = r;
        }
    }
}

// ---------------------------------------------------------------------------
extern "C" void kernel_launch(void* const* d_in, const int* in_sizes, int n_in,
                              void* d_out, int out_size)
{
    (void)in_sizes; (void)n_in; (void)out_size;
    const float* x        = (const float*)d_in[0];
    const float* attr_oh  = (const float*)d_in[1];
    const float* W_emb    = (const float*)d_in[2];
    const float* b_emb    = (const float*)d_in[3];
    const int*   h1       = (const int*)  d_in[4];
    const float* s1       = (const float*)d_in[5];
    const int*   h2       = (const int*)  d_in[6];
    const float* s2       = (const float*)d_in[7];
    const float* conv1_w  = (const float*)d_in[8];
    const float* conv2_w  = (const float*)d_in[9];

    float* out      = (float*)d_out;
    float* out_map  = out;               // [64,784]
    float* out_feat = out + BB * HW;     // [64,256,784]

    const int sh1 = (32 * ATTRN + 4 * ATTRN) * 4;                   // ~43.2 KB
    const int sh2 = 32 * 257 * 4 + 32768 + 2 * 512 * 8;             // ~73.9 KB
    const int sh3 = CC * ASTRIDE * 4 + 16 * 128 * 8
                  + 128 * 16 + 32 * 16 + O1 * 4;                    // ~55.9 KB
    cudaFuncSetAttribute(k1_emb,  cudaFuncAttributeMaxDynamicSharedMemorySize, sh1);
    cudaFuncSetAttribute(k2_cm,   cudaFuncAttributeMaxDynamicSharedMemorySize, sh2);
    cudaFuncSetAttribute(k3_main, cudaFuncAttributeMaxDynamicSharedMemorySize, sh3);

    k1_emb<<<128, 128, sh1>>>(attr_oh, W_emb, b_emb, s1, x);
    k2_cm<<<dim3(8, 16), 256, sh2>>>(conv1_w, h1, h2, s2);
    k3_main<<<dim3(7, BB), 256, sh3>>>(x, conv2_w, out_map, out_feat);
}